// round 2
// baseline (speedup 1.0000x reference)
#include <cuda_runtime.h>
#include <math.h>

// Problem constants
#define Bn  8
#define Hn  512
#define Wn  512
#define KK  5
#define NK  25      // KK*KK
#define HIDc 32
#define OC  50      // 2*NK

#define HW (Hn*Wn)

// Tile config for the fused conv kernel
#define TX 32
#define TY 8
#define NTHREADS (TX*TY)

// Guidance scratch: [B][3][H][W]  (25 MB, static device allocation is allowed)
__device__ float g_guid[Bn * 3 * HW];

// ---------------------------------------------------------------------------
// Kernel 1: bilinear grid-sample warp + fb + weight  -> guidance [B,3,H,W]
// ---------------------------------------------------------------------------
__global__ __launch_bounds__(256)
void guidance_kernel(const float* __restrict__ v02,
                     const float* __restrict__ v20,
                     float* __restrict__ guid)
{
    int idx = blockIdx.x * blockDim.x + threadIdx.x;
    if (idx >= Bn * HW) return;
    int x = idx % Wn;
    int y = (idx / Wn) % Hn;
    int b = idx / HW;

    const float* v02b = v02 + b * 2 * HW;
    const float* v20b = v20 + b * 2 * HW;

    float f0 = v02b[y * Wn + x];
    float f1 = v02b[HW + y * Wn + x];

    // base grid in [-1,1]
    float gx = -1.0f + 2.0f * (float)x / (float)(Wn - 1);
    float gy = -1.0f + 2.0f * (float)y / (float)(Hn - 1);
    float sgx = gx + f0 / (Wn * 0.5f);
    float sgy = gy + f1 / (Hn * 0.5f);

    // to pixel coords (align_corners=True)
    float ix = (sgx + 1.0f) * 0.5f * (float)(Wn - 1);
    float iy = (sgy + 1.0f) * 0.5f * (float)(Hn - 1);

    float x0f = floorf(ix);
    float y0f = floorf(iy);
    int   x0  = (int)x0f;
    int   y0  = (int)y0f;
    float wx1 = ix - x0f;
    float wy1 = iy - y0f;
    float wx0 = 1.0f - wx1;
    float wy0 = 1.0f - wy1;

    float s0 = 0.0f, s1 = 0.0f;
#pragma unroll
    for (int cy = 0; cy < 2; cy++) {
        int   yc = y0 + cy;
        float wy = cy ? wy1 : wy0;
        bool  vy = (yc >= 0) && (yc <= Hn - 1);
        int   yi = min(max(yc, 0), Hn - 1);
#pragma unroll
        for (int cx = 0; cx < 2; cx++) {
            int   xc = x0 + cx;
            float wx = cx ? wx1 : wx0;
            bool  vx = (xc >= 0) && (xc <= Wn - 1);
            int   xi = min(max(xc, 0), Wn - 1);
            float wgt = (vx && vy) ? (wx * wy) : 0.0f;
            s0 += wgt * v20b[yi * Wn + xi];
            s1 += wgt * v20b[HW + yi * Wn + xi];
        }
    }

    float fb0 = f0 + s0;
    float fb1 = f1 + s1;
    float cons = sqrtf(fb0 * fb0 + fb1 * fb1);
    float wv = expf(-cons);

    float* gb = guid + b * 3 * HW;
    gb[y * Wn + x]          = fb0;
    gb[HW + y * Wn + x]     = fb1;
    gb[2 * HW + y * Wn + x] = wv;
}

// ---------------------------------------------------------------------------
// Kernel 2: fused 3x3 conv (3->32) + ReLU + 1x1 conv (32->50) + dynamic
//           5x5 kernel application over unfolded flow
// ---------------------------------------------------------------------------
__global__ __launch_bounds__(NTHREADS)
void refine_kernel(const float* __restrict__ v02,
                   const float* __restrict__ guid,
                   const float* __restrict__ w1,
                   const float* __restrict__ b1,
                   const float* __restrict__ w2,
                   const float* __restrict__ b2,
                   float* __restrict__ out)
{
    // Weights in shared memory (row-padded so float4 reads stay 16B-aligned)
    __shared__ __align__(16) float sW1[HIDc * 28];   // [32][27] padded to 28
    __shared__ float sB1[HIDc];
    __shared__ __align__(16) float sW2[OC * HIDc];   // [50][32]
    __shared__ float sB2[64];
    // Guidance tile with halo 1: [3][TY+2][TX+2]
    __shared__ float sG[3 * (TY + 2) * (TX + 2)];
    // Flow tile with halo 2: [2][TY+4][TX+4]
    __shared__ float sF[2 * (TY + 4) * (TX + 4)];

    const int tid = threadIdx.y * TX + threadIdx.x;
    const int bx = blockIdx.x * TX;
    const int by = blockIdx.y * TY;
    const int b  = blockIdx.z;

    // --- stage weights ---
    for (int i = tid; i < HIDc * 27; i += NTHREADS)
        sW1[(i / 27) * 28 + (i % 27)] = w1[i];
    if (tid < HIDc) { sW1[tid * 28 + 27] = 0.0f; sB1[tid] = b1[tid]; }
    for (int i = tid; i < OC * HIDc; i += NTHREADS)
        sW2[i] = w2[i];
    if (tid < OC) sB2[tid] = b2[tid];

    // --- stage guidance tile (zero OOB = conv zero padding) ---
    const float* gb = guid + b * 3 * HW;
    const int GW = TX + 2, GH = TY + 2;
    for (int i = tid; i < 3 * GH * GW; i += NTHREADS) {
        int c  = i / (GH * GW);
        int r  = i - c * (GH * GW);
        int yy = r / GW;
        int xx = r - yy * GW;
        int gyy = by + yy - 1;
        int gxx = bx + xx - 1;
        float v = 0.0f;
        if (gyy >= 0 && gyy < Hn && gxx >= 0 && gxx < Wn)
            v = gb[c * HW + gyy * Wn + gxx];
        sG[i] = v;
    }

    // --- stage flow tile (zero OOB = unfold zero padding) ---
    const float* fbase = v02 + b * 2 * HW;
    const int FW = TX + 4, FH = TY + 4;
    for (int i = tid; i < 2 * FH * FW; i += NTHREADS) {
        int c  = i / (FH * FW);
        int r  = i - c * (FH * FW);
        int yy = r / FW;
        int xx = r - yy * FW;
        int gyy = by + yy - 2;
        int gxx = bx + xx - 2;
        float v = 0.0f;
        if (gyy >= 0 && gyy < Hn && gxx >= 0 && gxx < Wn)
            v = fbase[c * HW + gyy * Wn + gxx];
        sF[i] = v;
    }

    __syncthreads();

    const int lx = threadIdx.x;
    const int ly = threadIdx.y;

    // gather 3x3x3 guidance neighborhood into registers (padded to 28)
    float g[28];
#pragma unroll
    for (int c = 0; c < 3; c++)
#pragma unroll
        for (int dy = 0; dy < 3; dy++)
#pragma unroll
            for (int dx = 0; dx < 3; dx++)
                g[c * 9 + dy * 3 + dx] =
                    sG[c * (GH * GW) + (ly + dy) * GW + (lx + dx)];
    g[27] = 0.0f;

    // 3x3 conv (3->32) + ReLU, vectorized weight reads
    float h[HIDc];
    const float4* w1v = (const float4*)sW1;
#pragma unroll
    for (int j = 0; j < HIDc; j++) {
        float acc = sB1[j];
#pragma unroll
        for (int q = 0; q < 7; q++) {
            float4 wq = w1v[j * 7 + q];
            acc += wq.x * g[q * 4 + 0];
            acc += wq.y * g[q * 4 + 1];
            acc += wq.z * g[q * 4 + 2];
            acc += wq.w * g[q * 4 + 3];
        }
        h[j] = fmaxf(acc, 0.0f);
    }

    // 1x1 conv (32->50) fused with dynamic-kernel application
    float out0 = 0.0f, out1 = 0.0f;
    const float4* w2v = (const float4*)sW2;
#pragma unroll 1
    for (int ki = 0; ki < KK; ki++) {
#pragma unroll
        for (int kj = 0; kj < KK; kj++) {
            int k = ki * KK + kj;
            float ker0 = sB2[k];
            float ker1 = sB2[NK + k];
#pragma unroll
            for (int q = 0; q < 8; q++) {
                float4 wa = w2v[k * 8 + q];
                float4 wb = w2v[(NK + k) * 8 + q];
                ker0 += wa.x * h[4 * q + 0];
                ker0 += wa.y * h[4 * q + 1];
                ker0 += wa.z * h[4 * q + 2];
                ker0 += wa.w * h[4 * q + 3];
                ker1 += wb.x * h[4 * q + 0];
                ker1 += wb.y * h[4 * q + 1];
                ker1 += wb.z * h[4 * q + 2];
                ker1 += wb.w * h[4 * q + 3];
            }
            float p0 = sF[0 * (FH * FW) + (ly + ki) * FW + (lx + kj)];
            float p1 = sF[1 * (FH * FW) + (ly + ki) * FW + (lx + kj)];
            out0 += ker0 * p0;
            out1 += ker1 * p1;
        }
    }

    int oy = by + ly;
    int ox = bx + lx;
    out[b * 2 * HW + oy * Wn + ox]      = out0;
    out[b * 2 * HW + HW + oy * Wn + ox] = out1;
}

// ---------------------------------------------------------------------------
// Launch
// ---------------------------------------------------------------------------
extern "C" void kernel_launch(void* const* d_in, const int* in_sizes, int n_in,
                              void* d_out, int out_size)
{
    const float* v02 = (const float*)d_in[0];
    const float* v20 = (const float*)d_in[1];
    const float* w1  = (const float*)d_in[2];
    const float* b1  = (const float*)d_in[3];
    const float* w2  = (const float*)d_in[4];
    const float* b2  = (const float*)d_in[5];
    float* out = (float*)d_out;

    float* guid;
    cudaGetSymbolAddress((void**)&guid, g_guid);

    {
        int total = Bn * HW;
        int threads = 256;
        int blocks = (total + threads - 1) / threads;
        guidance_kernel<<<blocks, threads>>>(v02, v20, guid);
    }
    {
        dim3 block(TX, TY, 1);
        dim3 grid(Wn / TX, Hn / TY, Bn);
        refine_kernel<<<grid, block>>>(v02, guid, w1, b1, w2, b2, out);
    }
}

// round 3
// speedup vs baseline: 1.1785x; 1.1785x over previous
#include <cuda_runtime.h>
#include <math.h>

// Problem constants
#define Bn  8
#define Hn  512
#define Wn  512
#define KK  5
#define NK  25      // KK*KK
#define HIDc 32
#define OC  50      // 2*NK

#define HW (Hn*Wn)

// Tile config for the fused conv kernel: 32x8 pixel tile, 32x4 threads,
// each thread computes 2 vertically adjacent pixels.
#define TX 32
#define TYT 4              // thread rows
#define TYP 8              // pixel rows per tile (2 per thread)
#define NTHREADS (TX*TYT)  // 128

// Guidance scratch: [B][3][H][W]
__device__ float g_guid[Bn * 3 * HW];

// ---------------------------------------------------------------------------
// Kernel 1: bilinear grid-sample warp + fb + weight  -> guidance [B,3,H,W]
// ---------------------------------------------------------------------------
__global__ __launch_bounds__(256)
void guidance_kernel(const float* __restrict__ v02,
                     const float* __restrict__ v20,
                     float* __restrict__ guid)
{
    int idx = blockIdx.x * blockDim.x + threadIdx.x;
    if (idx >= Bn * HW) return;
    int x = idx % Wn;
    int y = (idx / Wn) % Hn;
    int b = idx / HW;

    const float* v02b = v02 + b * 2 * HW;
    const float* v20b = v20 + b * 2 * HW;

    float f0 = v02b[y * Wn + x];
    float f1 = v02b[HW + y * Wn + x];

    float gx = -1.0f + 2.0f * (float)x / (float)(Wn - 1);
    float gy = -1.0f + 2.0f * (float)y / (float)(Hn - 1);
    float sgx = gx + f0 / (Wn * 0.5f);
    float sgy = gy + f1 / (Hn * 0.5f);

    float ix = (sgx + 1.0f) * 0.5f * (float)(Wn - 1);
    float iy = (sgy + 1.0f) * 0.5f * (float)(Hn - 1);

    float x0f = floorf(ix);
    float y0f = floorf(iy);
    int   x0  = (int)x0f;
    int   y0  = (int)y0f;
    float wx1 = ix - x0f;
    float wy1 = iy - y0f;
    float wx0 = 1.0f - wx1;
    float wy0 = 1.0f - wy1;

    float s0 = 0.0f, s1 = 0.0f;
#pragma unroll
    for (int cy = 0; cy < 2; cy++) {
        int   yc = y0 + cy;
        float wy = cy ? wy1 : wy0;
        bool  vy = (yc >= 0) && (yc <= Hn - 1);
        int   yi = min(max(yc, 0), Hn - 1);
#pragma unroll
        for (int cx = 0; cx < 2; cx++) {
            int   xc = x0 + cx;
            float wx = cx ? wx1 : wx0;
            bool  vx = (xc >= 0) && (xc <= Wn - 1);
            int   xi = min(max(xc, 0), Wn - 1);
            float wgt = (vx && vy) ? (wx * wy) : 0.0f;
            s0 += wgt * v20b[yi * Wn + xi];
            s1 += wgt * v20b[HW + yi * Wn + xi];
        }
    }

    float fb0 = f0 + s0;
    float fb1 = f1 + s1;
    float cons = sqrtf(fb0 * fb0 + fb1 * fb1);
    float wv = expf(-cons);

    float* gb = guid + b * 3 * HW;
    gb[y * Wn + x]          = fb0;
    gb[HW + y * Wn + x]     = fb1;
    gb[2 * HW + y * Wn + x] = wv;
}

// ---------------------------------------------------------------------------
// Kernel 2: fused 3x3 conv (3->32) + ReLU + 1x1 conv (32->50) + dynamic
//           5x5 kernel application.  2 pixels per thread (vertical pair) to
//           amortize shared-memory weight reads (the measured bottleneck).
// ---------------------------------------------------------------------------
__global__ __launch_bounds__(NTHREADS, 4)
void refine_kernel(const float* __restrict__ v02,
                   const float* __restrict__ guid,
                   const float* __restrict__ w1,
                   const float* __restrict__ b1,
                   const float* __restrict__ w2,
                   const float* __restrict__ b2,
                   float* __restrict__ out)
{
    __shared__ __align__(16) float sW1[HIDc * 28];   // [32][27] padded to 28
    __shared__ float sB1[HIDc];
    __shared__ __align__(16) float sW2[OC * HIDc];   // [50][32]
    __shared__ float sB2[64];
    // Guidance tile with halo 1: [3][TYP+2][TX+2]
    __shared__ float sG[3 * (TYP + 2) * (TX + 2)];
    // Flow tile with halo 2: [2][TYP+4][TX+4]
    __shared__ float sF[2 * (TYP + 4) * (TX + 4)];

    const int tid = threadIdx.y * TX + threadIdx.x;
    const int bx = blockIdx.x * TX;
    const int by = blockIdx.y * TYP;
    const int b  = blockIdx.z;

    // --- stage weights ---
    for (int i = tid; i < HIDc * 27; i += NTHREADS)
        sW1[(i / 27) * 28 + (i % 27)] = w1[i];
    if (tid < HIDc) { sW1[tid * 28 + 27] = 0.0f; sB1[tid] = b1[tid]; }
    for (int i = tid; i < OC * HIDc; i += NTHREADS)
        sW2[i] = w2[i];
    if (tid < OC) sB2[tid] = b2[tid];

    // --- stage guidance tile (zero OOB = conv zero padding) ---
    const float* gb = guid + b * 3 * HW;
    const int GW = TX + 2, GH = TYP + 2;
    for (int i = tid; i < 3 * GH * GW; i += NTHREADS) {
        int c  = i / (GH * GW);
        int r  = i - c * (GH * GW);
        int yy = r / GW;
        int xx = r - yy * GW;
        int gyy = by + yy - 1;
        int gxx = bx + xx - 1;
        float v = 0.0f;
        if (gyy >= 0 && gyy < Hn && gxx >= 0 && gxx < Wn)
            v = gb[c * HW + gyy * Wn + gxx];
        sG[i] = v;
    }

    // --- stage flow tile (zero OOB = unfold zero padding) ---
    const float* fbase = v02 + b * 2 * HW;
    const int FW = TX + 4, FH = TYP + 4;
    for (int i = tid; i < 2 * FH * FW; i += NTHREADS) {
        int c  = i / (FH * FW);
        int r  = i - c * (FH * FW);
        int yy = r / FW;
        int xx = r - yy * FW;
        int gyy = by + yy - 2;
        int gxx = bx + xx - 2;
        float v = 0.0f;
        if (gyy >= 0 && gyy < Hn && gxx >= 0 && gxx < Wn)
            v = fbase[c * HW + gyy * Wn + gxx];
        sF[i] = v;
    }

    __syncthreads();

    const int lx = threadIdx.x;
    const int py = threadIdx.y * 2;   // tile-local row of pixel 0 (pixel 1 = py+1)

    // gather union of both pixels' 3x3x3 guidance neighborhoods:
    // [3 ch][4 rows][3 cols] = 36 registers
    float gg[36];
#pragma unroll
    for (int c = 0; c < 3; c++)
#pragma unroll
        for (int dy = 0; dy < 4; dy++)
#pragma unroll
            for (int dx = 0; dx < 3; dx++)
                gg[c * 12 + dy * 3 + dx] =
                    sG[c * (GH * GW) + (py + dy) * GW + (lx + dx)];

    // 3x3 conv (3->32) + ReLU for BOTH pixels with one weight read
    float h0[HIDc], h1[HIDc];
    const float4* w1v = (const float4*)sW1;
#pragma unroll
    for (int j = 0; j < HIDc; j++) {
        float a0 = sB1[j];
        float a1 = a0;
#pragma unroll
        for (int q = 0; q < 7; q++) {
            float4 wq = w1v[j * 7 + q];
            float we[4] = {wq.x, wq.y, wq.z, wq.w};
#pragma unroll
            for (int e = 0; e < 4; e++) {
                int idx = 4 * q + e;
                if (idx < 27) {
                    int gi = idx + 3 * (idx / 9);   // map 27-index -> 36-index
                    a0 += we[e] * gg[gi];
                    a1 += we[e] * gg[gi + 3];       // pixel1 = one row down
                }
            }
        }
        h0[j] = fmaxf(a0, 0.0f);
        h1[j] = fmaxf(a1, 0.0f);
    }

    // 1x1 conv (32->50) fused with dynamic-kernel application, both pixels
    float o00 = 0.0f, o01 = 0.0f;   // pixel0/pixel1, channel 0
    float o10 = 0.0f, o11 = 0.0f;   // pixel0/pixel1, channel 1
    const float4* w2v = (const float4*)sW2;
#pragma unroll 1
    for (int ki = 0; ki < KK; ki++) {
#pragma unroll
        for (int kj = 0; kj < KK; kj++) {
            int k = ki * KK + kj;
            float kb0 = sB2[k];
            float kb1 = sB2[NK + k];
            float k0p0 = kb0, k0p1 = kb0;
            float k1p0 = kb1, k1p1 = kb1;
#pragma unroll
            for (int q = 0; q < 8; q++) {
                float4 wa = w2v[k * 8 + q];
                float4 wb = w2v[(NK + k) * 8 + q];
                k0p0 += wa.x * h0[4 * q + 0];
                k0p0 += wa.y * h0[4 * q + 1];
                k0p0 += wa.z * h0[4 * q + 2];
                k0p0 += wa.w * h0[4 * q + 3];
                k0p1 += wa.x * h1[4 * q + 0];
                k0p1 += wa.y * h1[4 * q + 1];
                k0p1 += wa.z * h1[4 * q + 2];
                k0p1 += wa.w * h1[4 * q + 3];
                k1p0 += wb.x * h0[4 * q + 0];
                k1p0 += wb.y * h0[4 * q + 1];
                k1p0 += wb.z * h0[4 * q + 2];
                k1p0 += wb.w * h0[4 * q + 3];
                k1p1 += wb.x * h1[4 * q + 0];
                k1p1 += wb.y * h1[4 * q + 1];
                k1p1 += wb.z * h1[4 * q + 2];
                k1p1 += wb.w * h1[4 * q + 3];
            }
            float p00 = sF[0 * (FH * FW) + (py + ki) * FW + (lx + kj)];
            float p01 = sF[0 * (FH * FW) + (py + 1 + ki) * FW + (lx + kj)];
            float p10 = sF[1 * (FH * FW) + (py + ki) * FW + (lx + kj)];
            float p11 = sF[1 * (FH * FW) + (py + 1 + ki) * FW + (lx + kj)];
            o00 += k0p0 * p00;
            o01 += k0p1 * p01;
            o10 += k1p0 * p10;
            o11 += k1p1 * p11;
        }
    }

    int oy = by + py;
    int ox = bx + lx;
    float* ob = out + b * 2 * HW;
    ob[oy * Wn + ox]            = o00;
    ob[(oy + 1) * Wn + ox]      = o01;
    ob[HW + oy * Wn + ox]       = o10;
    ob[HW + (oy + 1) * Wn + ox] = o11;
}

// ---------------------------------------------------------------------------
// Launch
// ---------------------------------------------------------------------------
extern "C" void kernel_launch(void* const* d_in, const int* in_sizes, int n_in,
                              void* d_out, int out_size)
{
    const float* v02 = (const float*)d_in[0];
    const float* v20 = (const float*)d_in[1];
    const float* w1  = (const float*)d_in[2];
    const float* b1  = (const float*)d_in[3];
    const float* w2  = (const float*)d_in[4];
    const float* b2  = (const float*)d_in[5];
    float* out = (float*)d_out;

    float* guid;
    cudaGetSymbolAddress((void**)&guid, g_guid);

    {
        int total = Bn * HW;
        int threads = 256;
        int blocks = (total + threads - 1) / threads;
        guidance_kernel<<<blocks, threads>>>(v02, v20, guid);
    }
    {
        dim3 block(TX, TYT, 1);
        dim3 grid(Wn / TX, Hn / TYP, Bn);
        refine_kernel<<<grid, block>>>(v02, guid, w1, b1, w2, b2, out);
    }
}

// round 4
// speedup vs baseline: 1.2678x; 1.0758x over previous
#include <cuda_runtime.h>
#include <math.h>

// Problem constants
#define Bn  8
#define Hn  512
#define Wn  512
#define KK  5
#define NK  25      // KK*KK
#define HIDc 32
#define OC  50      // 2*NK

#define HW (Hn*Wn)

// Tile config: 32x8 pixel tile, 32x4 threads, 2 vertical pixels per thread.
#define TX 32
#define TYT 4
#define TYP 8
#define NTHREADS (TX*TYT)  // 128

// Guidance scratch: [B][3][H][W]
__device__ float g_guid[Bn * 3 * HW];

// ---------------------------------------------------------------------------
// packed f32x2 helpers (Blackwell)
// ---------------------------------------------------------------------------
__device__ __forceinline__ unsigned long long pk2(float lo, float hi) {
    unsigned long long r;
    asm("mov.b64 %0, {%1,%2};" : "=l"(r) : "f"(lo), "f"(hi));
    return r;
}
__device__ __forceinline__ unsigned long long dup2(float v) {
    unsigned long long r;
    asm("mov.b64 %0, {%1,%1};" : "=l"(r) : "f"(v));
    return r;
}
__device__ __forceinline__ unsigned long long fma2(unsigned long long a,
                                                   unsigned long long b,
                                                   unsigned long long c) {
    unsigned long long d;
    asm("fma.rn.f32x2 %0, %1, %2, %3;" : "=l"(d) : "l"(a), "l"(b), "l"(c));
    return d;
}
__device__ __forceinline__ float2 unpk(unsigned long long v) {
    float2 f;
    asm("mov.b64 {%0,%1}, %2;" : "=f"(f.x), "=f"(f.y) : "l"(v));
    return f;
}

// ---------------------------------------------------------------------------
// Kernel 1: bilinear grid-sample warp + fb + weight  -> guidance [B,3,H,W]
// ---------------------------------------------------------------------------
__global__ __launch_bounds__(256)
void guidance_kernel(const float* __restrict__ v02,
                     const float* __restrict__ v20,
                     float* __restrict__ guid)
{
    int idx = blockIdx.x * blockDim.x + threadIdx.x;
    if (idx >= Bn * HW) return;
    int x = idx % Wn;
    int y = (idx / Wn) % Hn;
    int b = idx / HW;

    const float* v02b = v02 + b * 2 * HW;
    const float* v20b = v20 + b * 2 * HW;

    float f0 = v02b[y * Wn + x];
    float f1 = v02b[HW + y * Wn + x];

    float gx = -1.0f + 2.0f * (float)x / (float)(Wn - 1);
    float gy = -1.0f + 2.0f * (float)y / (float)(Hn - 1);
    float sgx = gx + f0 / (Wn * 0.5f);
    float sgy = gy + f1 / (Hn * 0.5f);

    float ix = (sgx + 1.0f) * 0.5f * (float)(Wn - 1);
    float iy = (sgy + 1.0f) * 0.5f * (float)(Hn - 1);

    float x0f = floorf(ix);
    float y0f = floorf(iy);
    int   x0  = (int)x0f;
    int   y0  = (int)y0f;
    float wx1 = ix - x0f;
    float wy1 = iy - y0f;
    float wx0 = 1.0f - wx1;
    float wy0 = 1.0f - wy1;

    float s0 = 0.0f, s1 = 0.0f;
#pragma unroll
    for (int cy = 0; cy < 2; cy++) {
        int   yc = y0 + cy;
        float wy = cy ? wy1 : wy0;
        bool  vy = (yc >= 0) && (yc <= Hn - 1);
        int   yi = min(max(yc, 0), Hn - 1);
#pragma unroll
        for (int cx = 0; cx < 2; cx++) {
            int   xc = x0 + cx;
            float wx = cx ? wx1 : wx0;
            bool  vx = (xc >= 0) && (xc <= Wn - 1);
            int   xi = min(max(xc, 0), Wn - 1);
            float wgt = (vx && vy) ? (wx * wy) : 0.0f;
            s0 += wgt * v20b[yi * Wn + xi];
            s1 += wgt * v20b[HW + yi * Wn + xi];
        }
    }

    float fb0 = f0 + s0;
    float fb1 = f1 + s1;
    float cons = sqrtf(fb0 * fb0 + fb1 * fb1);
    float wv = expf(-cons);

    float* gb = guid + b * 3 * HW;
    gb[y * Wn + x]          = fb0;
    gb[HW + y * Wn + x]     = fb1;
    gb[2 * HW + y * Wn + x] = wv;
}

// ---------------------------------------------------------------------------
// Kernel 2: fused conv3x3(3->32)+ReLU + conv1x1(32->50) + dynamic 5x5 apply.
// 2 pixels per thread, all FMA work done as packed f32x2 (FFMA2).
// ---------------------------------------------------------------------------
__global__ __launch_bounds__(NTHREADS, 4)
void refine_kernel(const float* __restrict__ v02,
                   const float* __restrict__ guid,
                   const float* __restrict__ w1,
                   const float* __restrict__ b1,
                   const float* __restrict__ w2,
                   const float* __restrict__ b2,
                   float* __restrict__ out)
{
    // W1 rearranged per input channel: sW1c[c][j][12] (9 weights + 3 zero pad)
    __shared__ __align__(16) float sW1c[3 * HIDc * 12];
    __shared__ float sB1[HIDc];
    __shared__ __align__(16) float sW2[OC * HIDc];   // [50][32]
    __shared__ float sB2[64];
    // Guidance tile with halo 1: [3][TYP+2][TX+2]
    __shared__ float sG[3 * (TYP + 2) * (TX + 2)];
    // Flow tile with halo 2: [2][TYP+4][TX+4]
    __shared__ float sF[2 * (TYP + 4) * (TX + 4)];

    const int tid = threadIdx.y * TX + threadIdx.x;
    const int bx = blockIdx.x * TX;
    const int by = blockIdx.y * TYP;
    const int b  = blockIdx.z;

    // --- stage weights ---
    // w1 global layout: [j][c][3][3] -> j*27 + c*9 + s
    for (int i = tid; i < 3 * HIDc * 12; i += NTHREADS) {
        int s  = i % 12;
        int j  = (i / 12) % HIDc;
        int c  = i / (12 * HIDc);
        sW1c[i] = (s < 9) ? w1[j * 27 + c * 9 + s] : 0.0f;
    }
    if (tid < HIDc) sB1[tid] = b1[tid];
    for (int i = tid; i < OC * HIDc; i += NTHREADS)
        sW2[i] = w2[i];
    if (tid < OC) sB2[tid] = b2[tid];

    // --- stage guidance tile (zero OOB = conv zero padding) ---
    const float* gb = guid + b * 3 * HW;
    const int GW = TX + 2, GH = TYP + 2;
    for (int i = tid; i < 3 * GH * GW; i += NTHREADS) {
        int c  = i / (GH * GW);
        int r  = i - c * (GH * GW);
        int yy = r / GW;
        int xx = r - yy * GW;
        int gyy = by + yy - 1;
        int gxx = bx + xx - 1;
        float v = 0.0f;
        if (gyy >= 0 && gyy < Hn && gxx >= 0 && gxx < Wn)
            v = gb[c * HW + gyy * Wn + gxx];
        sG[i] = v;
    }

    // --- stage flow tile (zero OOB = unfold zero padding) ---
    const float* fbase = v02 + b * 2 * HW;
    const int FW = TX + 4, FH = TYP + 4;
    for (int i = tid; i < 2 * FH * FW; i += NTHREADS) {
        int c  = i / (FH * FW);
        int r  = i - c * (FH * FW);
        int yy = r / FW;
        int xx = r - yy * FW;
        int gyy = by + yy - 2;
        int gxx = bx + xx - 2;
        float v = 0.0f;
        if (gyy >= 0 && gyy < Hn && gxx >= 0 && gxx < Wn)
            v = fbase[c * HW + gyy * Wn + gxx];
        sF[i] = v;
    }

    __syncthreads();

    const int lx = threadIdx.x;
    const int py = threadIdx.y * 2;   // tile-local row of pixel0 (pixel1 = py+1)

    // --- conv3x3 (3->32) + ReLU, both pixels packed as f32x2 ---
    unsigned long long A[HIDc];
#pragma unroll
    for (int j = 0; j < HIDc; j++)
        A[j] = dup2(sB1[j]);

#pragma unroll
    for (int c = 0; c < 3; c++) {
        // packed guidance pairs for this input channel (9 taps + 3 zero pad)
        unsigned long long gp[12];
#pragma unroll
        for (int dy = 0; dy < 3; dy++)
#pragma unroll
            for (int dx = 0; dx < 3; dx++) {
                float glo = sG[c * (GH * GW) + (py + dy) * GW + (lx + dx)];
                float ghi = sG[c * (GH * GW) + (py + 1 + dy) * GW + (lx + dx)];
                gp[dy * 3 + dx] = pk2(glo, ghi);
            }
        gp[9] = 0ull; gp[10] = 0ull; gp[11] = 0ull;

        const float4* wv = (const float4*)(sW1c + c * HIDc * 12);
#pragma unroll
        for (int j = 0; j < HIDc; j++) {
#pragma unroll
            for (int q = 0; q < 3; q++) {
                float4 w = wv[j * 3 + q];
                A[j] = fma2(dup2(w.x), gp[q * 4 + 0], A[j]);
                A[j] = fma2(dup2(w.y), gp[q * 4 + 1], A[j]);
                A[j] = fma2(dup2(w.z), gp[q * 4 + 2], A[j]);
                A[j] = fma2(dup2(w.w), gp[q * 4 + 3], A[j]);
            }
        }
    }

    // ReLU both halves; A becomes the packed hidden vector hp
#pragma unroll
    for (int j = 0; j < HIDc; j++) {
        float2 a = unpk(A[j]);
        A[j] = pk2(fmaxf(a.x, 0.0f), fmaxf(a.y, 0.0f));
    }

    // --- 1x1 conv (32->50) fused with dynamic-kernel application ---
    unsigned long long O0 = 0ull;   // packed (out_ch0_p0, out_ch0_p1)
    unsigned long long O1 = 0ull;   // packed (out_ch1_p0, out_ch1_p1)
    const float4* w2v = (const float4*)sW2;
#pragma unroll 1
    for (int ki = 0; ki < KK; ki++) {
#pragma unroll
        for (int kj = 0; kj < KK; kj++) {
            int k = ki * KK + kj;
            unsigned long long P0 = dup2(sB2[k]);
            unsigned long long P1 = dup2(sB2[NK + k]);
#pragma unroll
            for (int q = 0; q < 8; q++) {
                float4 wa = w2v[k * 8 + q];
                float4 wb = w2v[(NK + k) * 8 + q];
                P0 = fma2(dup2(wa.x), A[4 * q + 0], P0);
                P0 = fma2(dup2(wa.y), A[4 * q + 1], P0);
                P0 = fma2(dup2(wa.z), A[4 * q + 2], P0);
                P0 = fma2(dup2(wa.w), A[4 * q + 3], P0);
                P1 = fma2(dup2(wb.x), A[4 * q + 0], P1);
                P1 = fma2(dup2(wb.y), A[4 * q + 1], P1);
                P1 = fma2(dup2(wb.z), A[4 * q + 2], P1);
                P1 = fma2(dup2(wb.w), A[4 * q + 3], P1);
            }
            // packed flow patches (pixel0, pixel1)
            float p00 = sF[0 * (FH * FW) + (py + ki) * FW + (lx + kj)];
            float p01 = sF[0 * (FH * FW) + (py + 1 + ki) * FW + (lx + kj)];
            float p10 = sF[1 * (FH * FW) + (py + ki) * FW + (lx + kj)];
            float p11 = sF[1 * (FH * FW) + (py + 1 + ki) * FW + (lx + kj)];
            O0 = fma2(P0, pk2(p00, p01), O0);
            O1 = fma2(P1, pk2(p10, p11), O1);
        }
    }

    float2 o0 = unpk(O0);
    float2 o1 = unpk(O1);
    int oy = by + py;
    int ox = bx + lx;
    float* ob = out + b * 2 * HW;
    ob[oy * Wn + ox]            = o0.x;
    ob[(oy + 1) * Wn + ox]      = o0.y;
    ob[HW + oy * Wn + ox]       = o1.x;
    ob[HW + (oy + 1) * Wn + ox] = o1.y;
}

// ---------------------------------------------------------------------------
// Launch
// ---------------------------------------------------------------------------
extern "C" void kernel_launch(void* const* d_in, const int* in_sizes, int n_in,
                              void* d_out, int out_size)
{
    const float* v02 = (const float*)d_in[0];
    const float* v20 = (const float*)d_in[1];
    const float* w1  = (const float*)d_in[2];
    const float* b1  = (const float*)d_in[3];
    const float* w2  = (const float*)d_in[4];
    const float* b2  = (const float*)d_in[5];
    float* out = (float*)d_out;

    float* guid;
    cudaGetSymbolAddress((void**)&guid, g_guid);

    {
        int total = Bn * HW;
        int threads = 256;
        int blocks = (total + threads - 1) / threads;
        guidance_kernel<<<blocks, threads>>>(v02, v20, guid);
    }
    {
        dim3 block(TX, TYT, 1);
        dim3 grid(Wn / TX, Hn / TYP, Bn);
        refine_kernel<<<grid, block>>>(v02, guid, w1, b1, w2, b2, out);
    }
}